// round 10
// baseline (speedup 1.0000x reference)
#include <cuda_runtime.h>
#include <cuda_bf16.h>
#include <math.h>
#include <stdint.h>

#define NPTS 160000
#define DIM  128
#define HID  512
#define KK   49
#define MBLK 1250   /* NPTS / 128 */

// ---------------- scratch (device globals; no allocations) ----------------
__device__ __nv_bfloat16 g_xln[(size_t)NPTS * DIM];
__device__ __nv_bfloat16 g_h[(size_t)NPTS * HID];
__device__ float g_part[(size_t)HID * MBLK];   // [col][rowblk]
__device__ float g_gx[HID];
__device__ float g_s[HID];
__device__ float g_b2s[DIM];
__device__ __nv_bfloat16 g_w1t[HID * DIM];   // w1 transposed [n][k], bf16
__device__ __nv_bfloat16 g_w2t[DIM * HID];   // s*w2 transposed [n][k], bf16
__device__ float g_x1[(size_t)NPTS * DIM];

// ---------------- helpers ----------------
__device__ __forceinline__ void mma16(float* c, const uint32_t* a, const uint32_t* b) {
    asm volatile(
        "mma.sync.aligned.m16n8k16.row.col.f32.bf16.bf16.f32 "
        "{%0,%1,%2,%3},{%4,%5,%6,%7},{%8,%9},{%0,%1,%2,%3};"
        : "+f"(c[0]), "+f"(c[1]), "+f"(c[2]), "+f"(c[3])
        : "r"(a[0]), "r"(a[1]), "r"(a[2]), "r"(a[3]), "r"(b[0]), "r"(b[1]));
}
__device__ __forceinline__ void ldsm4(uint32_t* d, uint32_t a) {
    asm volatile("ldmatrix.sync.aligned.m8n8.x4.shared.b16 {%0,%1,%2,%3},[%4];"
                 : "=r"(d[0]), "=r"(d[1]), "=r"(d[2]), "=r"(d[3]) : "r"(a));
}
#define CPA16(dst, src) \
    asm volatile("cp.async.cg.shared.global [%0], [%1], 16;\n" :: "r"(dst), "l"(src))
__device__ __forceinline__ float gelu_f(float x) {
    return 0.5f * x * (1.0f + erff(x * 0.7071067811865476f));
}

// ---------------- dwconv (sparse 7x7 depthwise) + LayerNorm -> bf16 -------
// 32 points/block; each warp accumulates 4 points concurrently (MLP=4).
__global__ __launch_bounds__(256) void dwconv_ln_kernel(
    const float* __restrict__ feats, const int* __restrict__ nbr,
    const float* __restrict__ w, const float* __restrict__ bdw,
    const float* __restrict__ lg, const float* __restrict__ lb, int depth)
{
    __shared__ float sw[KK * DIM];
    __shared__ int   snbr[32 * KK];
    const float* X = depth ? g_x1 : feats;
    const int tid = threadIdx.x;
    for (int i = tid; i < KK * DIM; i += 256) sw[i] = w[i];
    const int p0 = blockIdx.x * 32;
    for (int i = tid; i < 32 * KK; i += 256) snbr[i] = nbr[(size_t)p0 * KK + i];
    const int wid = tid >> 5, lane = tid & 31;
    const float4 bd = ((const float4*)bdw)[lane];
    const float4 gg = ((const float4*)lg)[lane];
    const float4 bb = ((const float4*)lb)[lane];
    __syncthreads();

    float4 acc[4];
    #pragma unroll
    for (int i = 0; i < 4; i++) acc[i] = bd;

    const float4* X4 = (const float4*)X;
    for (int k = 0; k < KK; k++) {
        const float4 wv = *(const float4*)(sw + k * DIM + lane * 4);
        #pragma unroll
        for (int i = 0; i < 4; i++) {
            int idx = snbr[(wid + 8 * i) * KK + k];   // uniform per warp
            if (idx < NPTS) {
                float4 x = __ldg(X4 + (size_t)idx * 32 + lane);
                acc[i].x += x.x * wv.x; acc[i].y += x.y * wv.y;
                acc[i].z += x.z * wv.z; acc[i].w += x.w * wv.w;
            }
        }
    }
    #pragma unroll
    for (int i = 0; i < 4; i++) {
        float s = acc[i].x + acc[i].y + acc[i].z + acc[i].w;
        #pragma unroll
        for (int o = 16; o > 0; o >>= 1) s += __shfl_xor_sync(0xffffffffu, s, o);
        float mu = s * (1.0f / DIM);
        float4 d = make_float4(acc[i].x - mu, acc[i].y - mu, acc[i].z - mu, acc[i].w - mu);
        float v = d.x * d.x + d.y * d.y + d.z * d.z + d.w * d.w;
        #pragma unroll
        for (int o = 16; o > 0; o >>= 1) v += __shfl_xor_sync(0xffffffffu, v, o);
        float inv = rsqrtf(v * (1.0f / DIM) + 1e-6f);
        __nv_bfloat162 y01 = make_bfloat162(
            __float2bfloat16(d.x * inv * gg.x + bb.x),
            __float2bfloat16(d.y * inv * gg.y + bb.y));
        __nv_bfloat162 y23 = make_bfloat162(
            __float2bfloat16(d.z * inv * gg.z + bb.z),
            __float2bfloat16(d.w * inv * gg.w + bb.w));
        __nv_bfloat162* dst =
            (__nv_bfloat162*)g_xln + (size_t)(p0 + wid + 8 * i) * 64 + lane * 2;
        dst[0] = y01; dst[1] = y23;
    }
}

// ---------------- transpose (+optional per-k scale) fp32[K][N]->bf16[N][K] -
__global__ void tr_bf16_kernel(const float* __restrict__ src,
                               __nv_bfloat16* __restrict__ dst,
                               const float* __restrict__ scale,
                               int K, int Nn)
{
    __shared__ float t[32][33];
    const int kb = blockIdx.x * 32, nb = blockIdx.y * 32;
    for (int r = threadIdx.y; r < 32; r += 8) {
        float v = src[(size_t)(kb + r) * Nn + nb + threadIdx.x];
        if (scale) v *= __ldg(scale + kb + r);
        t[r][threadIdx.x] = v;
    }
    __syncthreads();
    for (int r = threadIdx.y; r < 32; r += 8)
        dst[(size_t)(nb + r) * K + kb + threadIdx.x] =
            __float2bfloat16(t[threadIdx.x][r]);
}

// ---------------- stage loader -------------------------------------------
template<int ROWS, int KT>
__device__ __forceinline__ void load_tile(uint32_t base_sa, int st_u32,
                                          const __nv_bfloat16* G, int k0, int tid)
{
    #pragma unroll
    for (int i = 0; i < ROWS * 4 / 256; i++) {
        int c = tid + i * 256;
        int r = c >> 2, ch = c & 3;
        uint32_t dst = base_sa + (uint32_t)(st_u32 + r * 20 + ch * 4) * 4;
        CPA16(dst, G + (size_t)r * KT + k0 + ch * 8);
    }
}

// ---------------- bf16 tensor-core GEMM ----------------------------------
// CTA tile MT x NT, 8 warps of 64x64, 3-stage cp.async, single sync/iter.
// A bf16 [M][KTOT] row-major; Bt bf16 [N][KTOT] (n-major).
// EPI=1: g_h = bf16(gelu(A@B+bias)) (pitch HID), colsq partials -> part
// EPI=2: Out = A@B + bias + Xin (fp32, pitch DIM)
template<int MT, int NT, int KTOT, int EPI>
__global__ __launch_bounds__(256, 1) void gemm_bf16(
    const __nv_bfloat16* __restrict__ A, const __nv_bfloat16* __restrict__ Bt,
    const float* __restrict__ bias, const float* __restrict__ Xin,
    float* __restrict__ Out, float* __restrict__ part)
{
    constexpr int LDS32 = 20;
    constexpr int SA = MT * LDS32, SB = NT * LDS32;   // u32 per stage
    constexpr int KS = 32, NSTEP = KTOT / KS;
    constexpr int WGM = MT / 64;
    constexpr int PITCH = (EPI == 1) ? HID : DIM;
    extern __shared__ uint32_t dsm[];
    uint32_t* Bs0 = dsm + 3 * SA;
    __shared__ float s_cq[NT];

    const int tid = threadIdx.x;
    const int bm = blockIdx.x * MT;
    const int bn = blockIdx.y * NT;
    if (EPI == 1) { for (int i = tid; i < NT; i += 256) s_cq[i] = 0.0f; }

    const int w = tid >> 5, lane = tid & 31;
    const int l4 = lane >> 2, lm4 = lane & 3;
    const int wm = (w % WGM) * 64, wn = (w / WGM) * 64;
    const int lr = lane & 7, seg = lane >> 3;
    const uint32_t offA = ((lr + (seg & 1) * 8) * LDS32 + (seg >> 1) * 4) * 4;
    const uint32_t offB = ((lr + (seg >> 1) * 8) * LDS32 + (seg & 1) * 4) * 4;

    const uint32_t As_sa = (uint32_t)__cvta_generic_to_shared(dsm);
    const uint32_t Bs_sa = (uint32_t)__cvta_generic_to_shared(Bs0);

    const __nv_bfloat16* Ag = A + (size_t)bm * KTOT;
    const __nv_bfloat16* Bg = Bt + (size_t)bn * KTOT;

    float acc[4][8][4] = {};

    load_tile<MT, KTOT>(As_sa, 0, Ag, 0, tid);
    load_tile<NT, KTOT>(Bs_sa, 0, Bg, 0, tid);
    asm volatile("cp.async.commit_group;\n");
    load_tile<MT, KTOT>(As_sa, SA, Ag, KS, tid);
    load_tile<NT, KTOT>(Bs_sa, SB, Bg, KS, tid);
    asm volatile("cp.async.commit_group;\n");

    for (int s = 0; s < NSTEP; s++) {
        if (s + 1 < NSTEP) asm volatile("cp.async.wait_group 1;\n");
        else               asm volatile("cp.async.wait_group 0;\n");
        __syncthreads();
        if (s + 2 < NSTEP) {
            int sl = (s + 2) % 3;
            load_tile<MT, KTOT>(As_sa, sl * SA, Ag, (s + 2) * KS, tid);
            load_tile<NT, KTOT>(Bs_sa, sl * SB, Bg, (s + 2) * KS, tid);
            asm volatile("cp.async.commit_group;\n");
        }
        const int cs = s % 3;
        const uint32_t As_st = As_sa + (uint32_t)(cs * SA) * 4;
        const uint32_t Bs_st = Bs_sa + (uint32_t)(cs * SB) * 4;
        #pragma unroll
        for (int kb = 0; kb < 2; kb++) {
            uint32_t af[4][4], bf[8][2];
            #pragma unroll
            for (int mt = 0; mt < 4; mt++)
                ldsm4(af[mt], As_st + (uint32_t)((wm + mt * 16) * LDS32 + kb * 8) * 4 + offA);
            #pragma unroll
            for (int nh = 0; nh < 4; nh++) {
                uint32_t d[4];
                ldsm4(d, Bs_st + (uint32_t)((wn + nh * 16) * LDS32 + kb * 8) * 4 + offB);
                bf[2 * nh][0] = d[0]; bf[2 * nh][1] = d[1];
                bf[2 * nh + 1][0] = d[2]; bf[2 * nh + 1][1] = d[3];
            }
            #pragma unroll
            for (int mt = 0; mt < 4; mt++)
                #pragma unroll
                for (int nt = 0; nt < 8; nt++)
                    mma16(acc[mt][nt], af[mt], bf[nt]);
        }
        __syncthreads();
    }

    // ---------------- epilogue ----------------
    if (EPI == 1) {
        float cq[8][2] = {};
        #pragma unroll
        for (int mt = 0; mt < 4; mt++) {
            int r0 = bm + wm + mt * 16 + l4;
            #pragma unroll
            for (int nt = 0; nt < 8; nt++) {
                int c = bn + wn + nt * 8 + lm4 * 2;
                float b0 = __ldg(bias + c), b1 = __ldg(bias + c + 1);
                float t0 = gelu_f(acc[mt][nt][0] + b0);
                float t1 = gelu_f(acc[mt][nt][1] + b1);
                float t2 = gelu_f(acc[mt][nt][2] + b0);
                float t3 = gelu_f(acc[mt][nt][3] + b1);
                *((__nv_bfloat162*)(g_h + (size_t)r0 * PITCH + c)) =
                    make_bfloat162(__float2bfloat16(t0), __float2bfloat16(t1));
                *((__nv_bfloat162*)(g_h + (size_t)(r0 + 8) * PITCH + c)) =
                    make_bfloat162(__float2bfloat16(t2), __float2bfloat16(t3));
                cq[nt][0] += t0 * t0 + t2 * t2;
                cq[nt][1] += t1 * t1 + t3 * t3;
            }
        }
        #pragma unroll
        for (int nt = 0; nt < 8; nt++)
            #pragma unroll
            for (int j = 0; j < 2; j++) {
                float v = cq[nt][j];
                v += __shfl_xor_sync(0xffffffffu, v, 16);
                v += __shfl_xor_sync(0xffffffffu, v, 8);
                v += __shfl_xor_sync(0xffffffffu, v, 4);
                if (l4 == 0) atomicAdd(&s_cq[wn + nt * 8 + lm4 * 2 + j], v);
            }
        __syncthreads();
        for (int i = tid; i < NT; i += 256)
            part[(size_t)(bn + i) * MBLK + blockIdx.x] = s_cq[i];
    } else {
        #pragma unroll
        for (int mt = 0; mt < 4; mt++) {
            int r0 = bm + wm + mt * 16 + l4;
            #pragma unroll
            for (int nt = 0; nt < 8; nt++) {
                int c = bn + wn + nt * 8 + lm4 * 2;
                float b0 = __ldg(bias + c), b1 = __ldg(bias + c + 1);
                float2 x0 = *(const float2*)(Xin + (size_t)r0 * PITCH + c);
                float2 x1 = *(const float2*)(Xin + (size_t)(r0 + 8) * PITCH + c);
                *(float2*)(Out + (size_t)r0 * PITCH + c) =
                    make_float2(acc[mt][nt][0] + b0 + x0.x, acc[mt][nt][1] + b1 + x0.y);
                *(float2*)(Out + (size_t)(r0 + 8) * PITCH + c) =
                    make_float2(acc[mt][nt][2] + b0 + x1.x, acc[mt][nt][3] + b1 + x1.y);
            }
        }
    }
}

// ---------------- GRN column reduce: gx[j] = sqrt(sum_r part[j][r]) -------
__global__ __launch_bounds__(256) void reduce_gx_kernel()
{
    const int j = blockIdx.x;
    float sum = 0.0f;
    for (int r = threadIdx.x; r < MBLK; r += 256)
        sum += g_part[(size_t)j * MBLK + r];
    #pragma unroll
    for (int o = 16; o > 0; o >>= 1) sum += __shfl_xor_sync(0xffffffffu, sum, o);
    __shared__ float sm[8];
    if ((threadIdx.x & 31) == 0) sm[threadIdx.x >> 5] = sum;
    __syncthreads();
    if (threadIdx.x == 0) {
        float t = 0.0f;
        #pragma unroll
        for (int i = 0; i < 8; i++) t += sm[i];
        g_gx[j] = sqrtf(t);
    }
}

// ---------------- GRN finalize: s[k], b2' = b2 + grn_b @ W2 ---------------
__global__ void grn_finalize_kernel(const float* __restrict__ grn_g,
                                    const float* __restrict__ grn_b,
                                    const float* __restrict__ W2,
                                    const float* __restrict__ b2)
{
    const int j = threadIdx.x;   // 512 threads, 1 block
    __shared__ float sm[HID];
    __shared__ float sgb[HID];
    float gx = g_gx[j];
    sm[j] = gx;
    sgb[j] = __ldg(grn_b + j);
    __syncthreads();
    for (int o = 256; o > 0; o >>= 1) {
        if (j < o) sm[j] += sm[j + o];
        __syncthreads();
    }
    float mean = sm[0] * (1.0f / HID);
    g_s[j] = __ldg(grn_g + j) * (gx / (mean + 1e-6f)) + 1.0f;
    if (j < DIM) {
        float acc = __ldg(b2 + j);
        #pragma unroll 8
        for (int k = 0; k < HID; k++)
            acc += sgb[k] * __ldg(W2 + (size_t)k * DIM + j);
        g_b2s[j] = acc;
    }
}

// ---------------- launcher ----------------
extern "C" void kernel_launch(void* const* d_in, const int* in_sizes, int n_in,
                              void* d_out, int out_size) {
    const float* feats = (const float*)d_in[0];
    const float* w_dw  = (const float*)d_in[1];
    const float* b_dw  = (const float*)d_in[2];
    const float* ln_g  = (const float*)d_in[3];
    const float* ln_b  = (const float*)d_in[4];
    const float* w1    = (const float*)d_in[5];
    const float* b1    = (const float*)d_in[6];
    const float* grn_g = (const float*)d_in[7];
    const float* grn_b = (const float*)d_in[8];
    const float* w2    = (const float*)d_in[9];
    const float* b2    = (const float*)d_in[10];
    const int*   nbr   = (const int*)d_in[11];
    float* out = (float*)d_out;

    __nv_bfloat16 *p_xln, *p_h, *p_w1t, *p_w2t;
    float *p_part, *p_b2s, *p_x1, *p_s;
    cudaGetSymbolAddress((void**)&p_xln,  g_xln);
    cudaGetSymbolAddress((void**)&p_h,    g_h);
    cudaGetSymbolAddress((void**)&p_part, g_part);
    cudaGetSymbolAddress((void**)&p_w1t,  g_w1t);
    cudaGetSymbolAddress((void**)&p_w2t,  g_w2t);
    cudaGetSymbolAddress((void**)&p_b2s,  g_b2s);
    cudaGetSymbolAddress((void**)&p_x1,   g_x1);
    cudaGetSymbolAddress((void**)&p_s,    g_s);

    const int SMEM_BYTES = 3 * (128 + 256) * 20 * 4;   // 92160, both variants
    cudaFuncSetAttribute(gemm_bf16<128, 256, DIM, 1>,
                         cudaFuncAttributeMaxDynamicSharedMemorySize, SMEM_BYTES);
    cudaFuncSetAttribute(gemm_bf16<256, 128, HID, 2>,
                         cudaFuncAttributeMaxDynamicSharedMemorySize, SMEM_BYTES);

    dim3 tb(32, 8);
    for (int d = 0; d < 2; d++) {
        dwconv_ln_kernel<<<NPTS / 32, 256>>>(
            feats, nbr, w_dw + (size_t)d * KK * DIM, b_dw + d * DIM,
            ln_g + d * DIM, ln_b + d * DIM, d);
        tr_bf16_kernel<<<dim3(DIM / 32, HID / 32), tb>>>(
            w1 + (size_t)d * DIM * HID, p_w1t, (const float*)0, DIM, HID);
        gemm_bf16<128, 256, DIM, 1><<<dim3(MBLK, 2), 256, SMEM_BYTES>>>(
            p_xln, p_w1t, b1 + d * HID, (const float*)0, (float*)0, p_part);
        reduce_gx_kernel<<<HID, 256>>>();
        grn_finalize_kernel<<<1, HID>>>(grn_g + d * HID, grn_b + d * HID,
                                        w2 + (size_t)d * HID * DIM, b2 + d * DIM);
        tr_bf16_kernel<<<dim3(HID / 32, DIM / 32), tb>>>(
            w2 + (size_t)d * HID * DIM, p_w2t, p_s, HID, DIM);
        const float* Xin = d ? p_x1 : feats;
        float* Xout = d ? out : p_x1;
        gemm_bf16<256, 128, HID, 2><<<dim3(NPTS / 256, 1), 256, SMEM_BYTES>>>(
            p_h, p_w2t, p_b2s, Xin, Xout, (float*)0);
    }
}

// round 12
// speedup vs baseline: 1.1374x; 1.1374x over previous
#include <cuda_runtime.h>
#include <cuda_bf16.h>
#include <math.h>
#include <stdint.h>

#define NPTS 160000
#define DIM  128
#define HID  512
#define KK   49
#define MBLK 1250   /* NPTS / 128 */

// ---------------- scratch (device globals; no allocations) ----------------
__device__ __nv_bfloat16 g_xln[(size_t)NPTS * DIM];
__device__ __nv_bfloat16 g_h[(size_t)NPTS * HID];
__device__ float g_part[(size_t)HID * MBLK];   // [col][rowblk]
__device__ float g_gx[HID];
__device__ float g_s[HID];
__device__ float g_b2s[DIM];
__device__ __nv_bfloat16 g_w1t[HID * DIM];   // w1 transposed [n][k], bf16
__device__ __nv_bfloat16 g_w2t[DIM * HID];   // s*w2 transposed [n][k], bf16
__device__ float g_x1[(size_t)NPTS * DIM];

// ---------------- helpers ----------------
__device__ __forceinline__ void mma16(float* c, const uint32_t* a, const uint32_t* b) {
    asm volatile(
        "mma.sync.aligned.m16n8k16.row.col.f32.bf16.bf16.f32 "
        "{%0,%1,%2,%3},{%4,%5,%6,%7},{%8,%9},{%0,%1,%2,%3};"
        : "+f"(c[0]), "+f"(c[1]), "+f"(c[2]), "+f"(c[3])
        : "r"(a[0]), "r"(a[1]), "r"(a[2]), "r"(a[3]), "r"(b[0]), "r"(b[1]));
}
__device__ __forceinline__ void ldsm4(uint32_t* d, uint32_t a) {
    asm volatile("ldmatrix.sync.aligned.m8n8.x4.shared.b16 {%0,%1,%2,%3},[%4];"
                 : "=r"(d[0]), "=r"(d[1]), "=r"(d[2]), "=r"(d[3]) : "r"(a));
}
__device__ __forceinline__ void ldsm2(uint32_t* d, uint32_t a) {
    asm volatile("ldmatrix.sync.aligned.m8n8.x2.shared.b16 {%0,%1},[%2];"
                 : "=r"(d[0]), "=r"(d[1]) : "r"(a));
}
#define CPA16(dst, src) \
    asm volatile("cp.async.cg.shared.global [%0], [%1], 16;\n" :: "r"(dst), "l"(src))
__device__ __forceinline__ float gelu_f(float x) {
    return 0.5f * x * (1.0f + erff(x * 0.7071067811865476f));
}

// ---------------- dwconv (sparse 7x7 depthwise) + LayerNorm -> bf16 -------
// 32 points/block; each warp accumulates 4 points concurrently (MLP=4).
__global__ __launch_bounds__(256) void dwconv_ln_kernel(
    const float* __restrict__ feats, const int* __restrict__ nbr,
    const float* __restrict__ w, const float* __restrict__ bdw,
    const float* __restrict__ lg, const float* __restrict__ lb, int depth)
{
    __shared__ float sw[KK * DIM];
    __shared__ int   snbr[32 * KK];
    const float* X = depth ? g_x1 : feats;
    const int tid = threadIdx.x;
    for (int i = tid; i < KK * DIM; i += 256) sw[i] = w[i];
    const int p0 = blockIdx.x * 32;
    for (int i = tid; i < 32 * KK; i += 256) snbr[i] = nbr[(size_t)p0 * KK + i];
    const int wid = tid >> 5, lane = tid & 31;
    const float4 bd = ((const float4*)bdw)[lane];
    const float4 gg = ((const float4*)lg)[lane];
    const float4 bb = ((const float4*)lb)[lane];
    __syncthreads();

    float4 acc[4];
    #pragma unroll
    for (int i = 0; i < 4; i++) acc[i] = bd;

    const float4* X4 = (const float4*)X;
    for (int k = 0; k < KK; k++) {
        const float4 wv = *(const float4*)(sw + k * DIM + lane * 4);
        #pragma unroll
        for (int i = 0; i < 4; i++) {
            int idx = snbr[(wid + 8 * i) * KK + k];   // uniform per warp
            if (idx < NPTS) {
                float4 x = __ldg(X4 + (size_t)idx * 32 + lane);
                acc[i].x += x.x * wv.x; acc[i].y += x.y * wv.y;
                acc[i].z += x.z * wv.z; acc[i].w += x.w * wv.w;
            }
        }
    }
    #pragma unroll
    for (int i = 0; i < 4; i++) {
        float s = acc[i].x + acc[i].y + acc[i].z + acc[i].w;
        #pragma unroll
        for (int o = 16; o > 0; o >>= 1) s += __shfl_xor_sync(0xffffffffu, s, o);
        float mu = s * (1.0f / DIM);
        float4 d = make_float4(acc[i].x - mu, acc[i].y - mu, acc[i].z - mu, acc[i].w - mu);
        float v = d.x * d.x + d.y * d.y + d.z * d.z + d.w * d.w;
        #pragma unroll
        for (int o = 16; o > 0; o >>= 1) v += __shfl_xor_sync(0xffffffffu, v, o);
        float inv = rsqrtf(v * (1.0f / DIM) + 1e-6f);
        __nv_bfloat162 y01 = make_bfloat162(
            __float2bfloat16(d.x * inv * gg.x + bb.x),
            __float2bfloat16(d.y * inv * gg.y + bb.y));
        __nv_bfloat162 y23 = make_bfloat162(
            __float2bfloat16(d.z * inv * gg.z + bb.z),
            __float2bfloat16(d.w * inv * gg.w + bb.w));
        __nv_bfloat162* dst =
            (__nv_bfloat162*)g_xln + (size_t)(p0 + wid + 8 * i) * 64 + lane * 2;
        dst[0] = y01; dst[1] = y23;
    }
}

// ---------------- transpose (+optional per-k scale) fp32[K][N]->bf16[N][K] -
__global__ void tr_bf16_kernel(const float* __restrict__ src,
                               __nv_bfloat16* __restrict__ dst,
                               const float* __restrict__ scale,
                               int K, int Nn)
{
    __shared__ float t[32][33];
    const int kb = blockIdx.x * 32, nb = blockIdx.y * 32;
    for (int r = threadIdx.y; r < 32; r += 8) {
        float v = src[(size_t)(kb + r) * Nn + nb + threadIdx.x];
        if (scale) v *= __ldg(scale + kb + r);
        t[r][threadIdx.x] = v;
    }
    __syncthreads();
    for (int r = threadIdx.y; r < 32; r += 8)
        dst[(size_t)(nb + r) * K + kb + threadIdx.x] =
            __float2bfloat16(t[threadIdx.x][r]);
}

// ---------------- bf16 tensor-core GEMM, 128x128 CTA, 64x32 warp tiles ----
// 3-stage cp.async pipeline, ldmatrix fragment loads, single sync per iter.
// A bf16 [M][KTOT] row-major; Bt bf16 [N][KTOT] (n-major).
// EPI=1: g_h = bf16(gelu(A@B+bias)), column-sumsq partials -> part [col][blk]
// EPI=2: Out = A@B + bias + Xin (fp32)
template<int KTOT, int NB, int EPI>
__global__ __launch_bounds__(256, 2) void gemm_bf16(
    const __nv_bfloat16* __restrict__ A, const __nv_bfloat16* __restrict__ Bt,
    const float* __restrict__ bias, const float* __restrict__ Xin,
    float* __restrict__ Out, float* __restrict__ part)
{
    constexpr int LDS32 = 20;               // b32 pitch per 32-elem bf16 row
    constexpr int STG = 2560;               // u32 per stage per array
    constexpr int KS = 32, NSTEP = KTOT / KS;
    extern __shared__ uint32_t dsm[];
    uint32_t* As = dsm;
    uint32_t* Bs = dsm + 3 * STG;
    __shared__ float s_cq[128];

    const int tid = threadIdx.x;
    const int bm = blockIdx.x * 128;
    const int bn = blockIdx.y * 128;
    if (EPI == 1 && tid < 128) s_cq[tid] = 0.0f;

    const int w = tid >> 5, lane = tid & 31;
    const int l4 = lane >> 2, lm4 = lane & 3;
    const int wm = (w & 1) * 64, wn = (w >> 1) * 32;
    const int lr = lane & 7, seg = lane >> 3;
    const uint32_t offA = ((lr + (seg & 1) * 8) * LDS32 + (seg >> 1) * 4) * 4;
    const uint32_t offB = (lr * LDS32 + (seg & 1) * 4) * 4;

    const uint32_t As_sa = (uint32_t)__cvta_generic_to_shared(As);
    const uint32_t Bs_sa = (uint32_t)__cvta_generic_to_shared(Bs);

    const __nv_bfloat16* Ag = A + (size_t)bm * KTOT;
    const __nv_bfloat16* Bg = Bt + (size_t)bn * KTOT;

    float acc[4][4][4] = {};

    // 512 16B-chunks per tile (128 rows x 4 chunks), 2 per thread
    #define LOAD_T(base_sa, st, G, k0) { \
        _Pragma("unroll") \
        for (int i = 0; i < 2; i++) { \
            int c = tid + i * 256; \
            int r = c >> 2, ch = c & 3; \
            uint32_t dst = base_sa + (uint32_t)((st) * STG + r * LDS32 + ch * 4) * 4; \
            CPA16(dst, G + (size_t)r * KTOT + (k0) + ch * 8); \
        } }

    LOAD_T(As_sa, 0, Ag, 0); LOAD_T(Bs_sa, 0, Bg, 0);
    asm volatile("cp.async.commit_group;\n");
    LOAD_T(As_sa, 1, Ag, KS); LOAD_T(Bs_sa, 1, Bg, KS);
    asm volatile("cp.async.commit_group;\n");

    for (int s = 0; s < NSTEP; s++) {
        if (s + 1 < NSTEP) asm volatile("cp.async.wait_group 1;\n");
        else               asm volatile("cp.async.wait_group 0;\n");
        __syncthreads();
        if (s + 2 < NSTEP) {
            int sl = (s + 2) % 3;
            LOAD_T(As_sa, sl, Ag, (s + 2) * KS);
            LOAD_T(Bs_sa, sl, Bg, (s + 2) * KS);
            asm volatile("cp.async.commit_group;\n");
        }
        const int cs = s % 3;
        const uint32_t As_st = As_sa + (uint32_t)cs * STG * 4;
        const uint32_t Bs_st = Bs_sa + (uint32_t)cs * STG * 4;
        #pragma unroll
        for (int kb = 0; kb < 2; kb++) {
            uint32_t af[4][4], bf[4][2];
            #pragma unroll
            for (int mt = 0; mt < 4; mt++)
                ldsm4(af[mt], As_st + (uint32_t)((wm + mt * 16) * LDS32 + kb * 8) * 4 + offA);
            #pragma unroll
            for (int nt = 0; nt < 4; nt++)
                ldsm2(bf[nt], Bs_st + (uint32_t)((wn + nt * 8) * LDS32 + kb * 8) * 4 + offB);
            #pragma unroll
            for (int mt = 0; mt < 4; mt++)
                #pragma unroll
                for (int nt = 0; nt < 4; nt++)
                    mma16(acc[mt][nt], af[mt], bf[nt]);
        }
    }
    #undef LOAD_T

    // ---------------- epilogue ----------------
    if (EPI == 1) {
        float cq[4][2] = {};
        #pragma unroll
        for (int mt = 0; mt < 4; mt++) {
            int r0 = bm + wm + mt * 16 + l4;
            #pragma unroll
            for (int nt = 0; nt < 4; nt++) {
                int c = bn + wn + nt * 8 + lm4 * 2;
                float b0 = __ldg(bias + c), b1 = __ldg(bias + c + 1);
                float t0 = gelu_f(acc[mt][nt][0] + b0);
                float t1 = gelu_f(acc[mt][nt][1] + b1);
                float t2 = gelu_f(acc[mt][nt][2] + b0);
                float t3 = gelu_f(acc[mt][nt][3] + b1);
                *((__nv_bfloat162*)(g_h + (size_t)r0 * NB + c)) =
                    make_bfloat162(__float2bfloat16(t0), __float2bfloat16(t1));
                *((__nv_bfloat162*)(g_h + (size_t)(r0 + 8) * NB + c)) =
                    make_bfloat162(__float2bfloat16(t2), __float2bfloat16(t3));
                cq[nt][0] += t0 * t0 + t2 * t2;
                cq[nt][1] += t1 * t1 + t3 * t3;
            }
        }
        #pragma unroll
        for (int nt = 0; nt < 4; nt++)
            #pragma unroll
            for (int j = 0; j < 2; j++) {
                float v = cq[nt][j];
                v += __shfl_xor_sync(0xffffffffu, v, 16);
                v += __shfl_xor_sync(0xffffffffu, v, 8);
                v += __shfl_xor_sync(0xffffffffu, v, 4);
                if (l4 == 0) atomicAdd(&s_cq[wn + nt * 8 + lm4 * 2 + j], v);
            }
        __syncthreads();
        if (tid < 128)
            part[(size_t)(bn + tid) * MBLK + blockIdx.x] = s_cq[tid];
    } else {
        #pragma unroll
        for (int mt = 0; mt < 4; mt++) {
            int r0 = bm + wm + mt * 16 + l4;
            #pragma unroll
            for (int nt = 0; nt < 4; nt++) {
                int c = bn + wn + nt * 8 + lm4 * 2;
                float b0 = __ldg(bias + c), b1 = __ldg(bias + c + 1);
                float2 x0 = *(const float2*)(Xin + (size_t)r0 * NB + c);
                float2 x1 = *(const float2*)(Xin + (size_t)(r0 + 8) * NB + c);
                *(float2*)(Out + (size_t)r0 * NB + c) =
                    make_float2(acc[mt][nt][0] + b0 + x0.x, acc[mt][nt][1] + b1 + x0.y);
                *(float2*)(Out + (size_t)(r0 + 8) * NB + c) =
                    make_float2(acc[mt][nt][2] + b0 + x1.x, acc[mt][nt][3] + b1 + x1.y);
            }
        }
    }
}

// ---------------- GRN column reduce: gx[j] = sqrt(sum_r part[j][r]) -------
__global__ __launch_bounds__(256) void reduce_gx_kernel()
{
    const int j = blockIdx.x;
    float sum = 0.0f;
    for (int r = threadIdx.x; r < MBLK; r += 256)
        sum += g_part[(size_t)j * MBLK + r];
    #pragma unroll
    for (int o = 16; o > 0; o >>= 1) sum += __shfl_xor_sync(0xffffffffu, sum, o);
    __shared__ float sm[8];
    if ((threadIdx.x & 31) == 0) sm[threadIdx.x >> 5] = sum;
    __syncthreads();
    if (threadIdx.x == 0) {
        float t = 0.0f;
        #pragma unroll
        for (int i = 0; i < 8; i++) t += sm[i];
        g_gx[j] = sqrtf(t);
    }
}

// ---------------- GRN finalize: s[k], b2' = b2 + grn_b @ W2 ---------------
__global__ void grn_finalize_kernel(const float* __restrict__ grn_g,
                                    const float* __restrict__ grn_b,
                                    const float* __restrict__ W2,
                                    const float* __restrict__ b2)
{
    const int j = threadIdx.x;   // 512 threads, 1 block
    __shared__ float sm[HID];
    __shared__ float sgb[HID];
    float gx = g_gx[j];
    sm[j] = gx;
    sgb[j] = __ldg(grn_b + j);
    __syncthreads();
    for (int o = 256; o > 0; o >>= 1) {
        if (j < o) sm[j] += sm[j + o];
        __syncthreads();
    }
    float mean = sm[0] * (1.0f / HID);
    g_s[j] = __ldg(grn_g + j) * (gx / (mean + 1e-6f)) + 1.0f;
    if (j < DIM) {
        float acc = __ldg(b2 + j);
        #pragma unroll 8
        for (int k = 0; k < HID; k++)
            acc += sgb[k] * __ldg(W2 + (size_t)k * DIM + j);
        g_b2s[j] = acc;
    }
}

// ---------------- launcher ----------------
extern "C" void kernel_launch(void* const* d_in, const int* in_sizes, int n_in,
                              void* d_out, int out_size) {
    const float* feats = (const float*)d_in[0];
    const float* w_dw  = (const float*)d_in[1];
    const float* b_dw  = (const float*)d_in[2];
    const float* ln_g  = (const float*)d_in[3];
    const float* ln_b  = (const float*)d_in[4];
    const float* w1    = (const float*)d_in[5];
    const float* b1    = (const float*)d_in[6];
    const float* grn_g = (const float*)d_in[7];
    const float* grn_b = (const float*)d_in[8];
    const float* w2    = (const float*)d_in[9];
    const float* b2    = (const float*)d_in[10];
    const int*   nbr   = (const int*)d_in[11];
    float* out = (float*)d_out;

    __nv_bfloat16 *p_xln, *p_h, *p_w1t, *p_w2t;
    float *p_part, *p_b2s, *p_x1, *p_s;
    cudaGetSymbolAddress((void**)&p_xln,  g_xln);
    cudaGetSymbolAddress((void**)&p_h,    g_h);
    cudaGetSymbolAddress((void**)&p_part, g_part);
    cudaGetSymbolAddress((void**)&p_w1t,  g_w1t);
    cudaGetSymbolAddress((void**)&p_w2t,  g_w2t);
    cudaGetSymbolAddress((void**)&p_b2s,  g_b2s);
    cudaGetSymbolAddress((void**)&p_x1,   g_x1);
    cudaGetSymbolAddress((void**)&p_s,    g_s);

    const int SMEM_BYTES = 3 * 2560 * 2 * 4;   // 61440
    cudaFuncSetAttribute(gemm_bf16<DIM, HID, 1>,
                         cudaFuncAttributeMaxDynamicSharedMemorySize, SMEM_BYTES);
    cudaFuncSetAttribute(gemm_bf16<HID, DIM, 2>,
                         cudaFuncAttributeMaxDynamicSharedMemorySize, SMEM_BYTES);

    dim3 tb(32, 8);
    for (int d = 0; d < 2; d++) {
        dwconv_ln_kernel<<<NPTS / 32, 256>>>(
            feats, nbr, w_dw + (size_t)d * KK * DIM, b_dw + d * DIM,
            ln_g + d * DIM, ln_b + d * DIM, d);
        tr_bf16_kernel<<<dim3(DIM / 32, HID / 32), tb>>>(
            w1 + (size_t)d * DIM * HID, p_w1t, (const float*)0, DIM, HID);
        gemm_bf16<DIM, HID, 1><<<dim3(MBLK, 4), 256, SMEM_BYTES>>>(
            p_xln, p_w1t, b1 + d * HID, (const float*)0, (float*)0, p_part);
        reduce_gx_kernel<<<HID, 256>>>();
        grn_finalize_kernel<<<1, HID>>>(grn_g + d * HID, grn_b + d * HID,
                                        w2 + (size_t)d * HID * DIM, b2 + d * DIM);
        tr_bf16_kernel<<<dim3(HID / 32, DIM / 32), tb>>>(
            w2 + (size_t)d * HID * DIM, p_w2t, p_s, HID, DIM);
        const float* Xin = d ? p_x1 : feats;
        float* Xout = d ? out : p_x1;
        gemm_bf16<HID, DIM, 2><<<dim3(MBLK, 1), 256, SMEM_BYTES>>>(
            p_h, p_w2t, p_b2s, Xin, Xout, (float*)0);
    }
}